// round 17
// baseline (speedup 1.0000x reference)
#include <cuda_runtime.h>
#include <cuda_fp16.h>
#include <stdint.h>
#include <math.h>

typedef unsigned int u32;
typedef unsigned long long u64;

#define NN 50000
#define EE 800000
#define ET (EE + NN)
#define TDIM 64
#define SCAN_TILE 4096   // 1024 threads x 4 elems

// ---------------- scratch (static device globals; no allocation) ----------------
__device__ int    g_deg[NN];
__device__ int    g_rowptr[NN + 1];
__device__ int    g_cursor[NN];
__device__ int    g_blocksum[64];
__device__ int    g_colsrc[ET];
__device__ float4 g_alphaE0[EE];
__device__ float4 g_alphaE1[EE];
__device__ float4 g_aE0c[ET];
__device__ float4 g_aE1c[ET];
__device__ float4 g_aCSR[ET];
__device__ __half g_xh[(size_t)NN * 128];
__device__ __half g_w0h[128 * 256];
__device__ __half g_w1h[256 * 64];
__device__ __half g_hh0[(size_t)NN * 256];
__device__ __half g_out0h[(size_t)NN * 256];
__device__ __half g_hh1[(size_t)NN * 64];
__device__ float4 g_ss0[NN], g_sd0[NN], g_ss1[NN], g_sd1[NN];
__device__ float4 g_ve0[TDIM];
__device__ float4 g_ve1[TDIM];
__device__ float4 g_self0, g_self1;

// ---------------- PTX helpers ----------------
__device__ __forceinline__ void ldsm_x4(u32& r0, u32& r1, u32& r2, u32& r3, u32 addr) {
    asm volatile("ldmatrix.sync.aligned.m8n8.x4.shared.b16 {%0,%1,%2,%3}, [%4];"
                 : "=r"(r0), "=r"(r1), "=r"(r2), "=r"(r3) : "r"(addr));
}
__device__ __forceinline__ void ldsm_x4_trans(u32& r0, u32& r1, u32& r2, u32& r3, u32 addr) {
    asm volatile("ldmatrix.sync.aligned.m8n8.x4.trans.shared.b16 {%0,%1,%2,%3}, [%4];"
                 : "=r"(r0), "=r"(r1), "=r"(r2), "=r"(r3) : "r"(addr));
}
__device__ __forceinline__ void mma16816(float& c0, float& c1, float& c2, float& c3,
                                         u32 a0, u32 a1, u32 a2, u32 a3,
                                         u32 b0, u32 b1) {
    asm volatile(
        "mma.sync.aligned.m16n8k16.row.col.f32.f16.f16.f32 "
        "{%0,%1,%2,%3}, {%4,%5,%6,%7}, {%8,%9}, {%0,%1,%2,%3};"
        : "+f"(c0), "+f"(c1), "+f"(c2), "+f"(c3)
        : "r"(a0), "r"(a1), "r"(a2), "r"(a3), "r"(b0), "r"(b1));
}
__device__ __forceinline__ void cp_async16(u32 saddr, const void* gaddr, int src_bytes) {
    asm volatile("cp.async.ca.shared.global [%0], [%1], 16, %2;"
                 :: "r"(saddr), "l"(gaddr), "r"(src_bytes));
}
#define CP_COMMIT()  asm volatile("cp.async.commit_group;")
#define CP_WAIT(n)   asm volatile("cp.async.wait_group %0;" :: "n"(n))

__device__ __forceinline__ void ffma2(u64& d, u64 a, u64 b) {
    asm("fma.rn.f32x2 %0, %1, %2, %0;" : "+l"(d) : "l"(a), "l"(b));
}
__device__ __forceinline__ u64 pack2(float lo, float hi) {
    u64 r;
    asm("mov.b64 %0, {%1, %2};" : "=l"(r) : "f"(lo), "f"(hi));
    return r;
}
__device__ __forceinline__ void unpack2(float& lo, float& hi, u64 v) {
    asm("mov.b64 {%0, %1}, %2;" : "=f"(lo), "=f"(hi) : "l"(v));
}

// ---------------- prep: ve + self vectors (1 block) ----------------
__global__ void prep_kernel(const float* __restrict__ le0, const float* __restrict__ ae0,
                            const float* __restrict__ le1, const float* __restrict__ ae1) {
    int tid = threadIdx.x;
    int td = tid >> 2, hh = tid & 3;
    float s0 = 0.f;
    for (int c = 0; c < 64; c++) s0 += le0[td * 256 + hh * 64 + c] * ae0[hh * 64 + c];
    ((float*)g_ve0)[td * 4 + hh] = s0;
    float s1 = 0.f;
    for (int c = 0; c < 16; c++) s1 += le1[td * 64 + hh * 16 + c] * ae1[hh * 16 + c];
    ((float*)g_ve1)[td * 4 + hh] = s1;
    __syncthreads();
    if (td == 0) {
        float a = 0.f, b = 0.f;
        for (int t2 = 0; t2 < TDIM; t2++) {
            a += ((float*)g_ve0)[t2 * 4 + hh];
            b += ((float*)g_ve1)[t2 * 4 + hh];
        }
        ((float*)&g_self0)[hh] = a;
        ((float*)&g_self1)[hh] = b;
    }
}

// ---------------- cvt: x, W0, W1 -> fp16 (s1 stream, feeds hgemm0 only) -----------
__global__ void cvt_kernel(const float* __restrict__ x, const float* __restrict__ W0,
                           const float* __restrict__ W1,
                           __half* __restrict__ xh, __half* __restrict__ w0h,
                           __half* __restrict__ w1h, int n) {
    int gid = blockIdx.x * 256 + threadIdx.x;
    int stride = gridDim.x * 256;
    int nx4 = n * 32;
    for (int i = gid; i < nx4; i += stride) {
        float4 v = *(const float4*)(x + (size_t)i * 4);
        *(__half2*)(xh + (size_t)i * 4) = __floats2half2_rn(v.x, v.y);
        *(__half2*)(xh + (size_t)i * 4 + 2) = __floats2half2_rn(v.z, v.w);
    }
    for (int i = gid; i < 8192; i += stride) {
        float4 v = *(const float4*)(W0 + (size_t)i * 4);
        *(__half2*)(w0h + (size_t)i * 4) = __floats2half2_rn(v.x, v.y);
        *(__half2*)(w0h + (size_t)i * 4 + 2) = __floats2half2_rn(v.z, v.w);
    }
    for (int i = gid; i < 4096; i += stride) {
        float4 v = *(const float4*)(W1 + (size_t)i * 4);
        *(__half2*)(w1h + (size_t)i * 4) = __floats2half2_rn(v.x, v.y);
        *(__half2*)(w1h + (size_t)i * 4 + 2) = __floats2half2_rn(v.z, v.w);
    }
}

// ---------------- per-edge time features + fused deg count, 4 edges/thread -----------
__global__ void edge_feat_kernel(const float* __restrict__ ts,
                                 const float* __restrict__ tw,
                                 const float* __restrict__ tb,
                                 const int* __restrict__ dst,
                                 int* __restrict__ deg,
                                 float4* __restrict__ aE0, float4* __restrict__ aE1,
                                 int e) {
    __shared__ float2 swb[TDIM];
    __shared__ u64 pv0a[TDIM], pv0b[TDIM], pv1a[TDIM], pv1b[TDIM];
    int tid = threadIdx.x;
    if (tid < TDIM) {
        swb[tid] = make_float2(tw[tid], tb[tid]);
        float4 v0 = g_ve0[tid];
        float4 v1 = g_ve1[tid];
        pv0a[tid] = pack2(v0.x, v0.y);
        pv0b[tid] = pack2(v0.z, v0.w);
        pv1a[tid] = pack2(v1.x, v1.y);
        pv1b[tid] = pack2(v1.z, v1.w);
    }
    __syncthreads();
    int base = blockIdx.x * 1024 + tid;
    float tt[4];
    #pragma unroll
    for (int q = 0; q < 4; q++) {
        int i = base + q * 256;
        tt[q] = (i < e) ? ts[i] : 0.f;
        if (i < e) atomicAdd(&deg[dst[i]], 1);
    }
    u64 acc0a[4], acc0b[4], acc1a[4], acc1b[4];
    #pragma unroll
    for (int q = 0; q < 4; q++) { acc0a[q] = 0; acc0b[q] = 0; acc1a[q] = 0; acc1b[q] = 0; }
    #pragma unroll 4
    for (int td = 0; td < TDIM; td++) {
        float2 wb = swb[td];
        float c0 = fabsf(__cosf(fmaf(tt[0], wb.x, wb.y)));
        float c1 = fabsf(__cosf(fmaf(tt[1], wb.x, wb.y)));
        float c2 = fabsf(__cosf(fmaf(tt[2], wb.x, wb.y)));
        float c3 = fabsf(__cosf(fmaf(tt[3], wb.x, wb.y)));
        u64 v0a = pv0a[td], v0b = pv0b[td], v1a = pv1a[td], v1b = pv1b[td];
        u64 cc0 = pack2(c0, c0), cc1 = pack2(c1, c1);
        u64 cc2 = pack2(c2, c2), cc3 = pack2(c3, c3);
        ffma2(acc0a[0], cc0, v0a); ffma2(acc0b[0], cc0, v0b);
        ffma2(acc1a[0], cc0, v1a); ffma2(acc1b[0], cc0, v1b);
        ffma2(acc0a[1], cc1, v0a); ffma2(acc0b[1], cc1, v0b);
        ffma2(acc1a[1], cc1, v1a); ffma2(acc1b[1], cc1, v1b);
        ffma2(acc0a[2], cc2, v0a); ffma2(acc0b[2], cc2, v0b);
        ffma2(acc1a[2], cc2, v1a); ffma2(acc1b[2], cc2, v1b);
        ffma2(acc0a[3], cc3, v0a); ffma2(acc0b[3], cc3, v0b);
        ffma2(acc1a[3], cc3, v1a); ffma2(acc1b[3], cc3, v1b);
    }
    #pragma unroll
    for (int q = 0; q < 4; q++) {
        int i = base + q * 256;
        if (i < e) {
            float4 r0, r1;
            unpack2(r0.x, r0.y, acc0a[q]); unpack2(r0.z, r0.w, acc0b[q]);
            unpack2(r1.x, r1.y, acc1a[q]); unpack2(r1.z, r1.w, acc1b[q]);
            aE0[i] = r0; aE1[i] = r1;
        }
    }
}

// ---------------- multi-block scan, phase 1 (adds self-loop +1 per node) -------------
__global__ void scan1_kernel(const int* __restrict__ deg, int* __restrict__ rowptr,
                             int* __restrict__ blocksum, int n) {
    __shared__ int wsum[32];
    int t = threadIdx.x;
    int lane = t & 31, wid = t >> 5;
    int base = blockIdx.x * SCAN_TILE + t * 4;
    int4 v = make_int4(0, 0, 0, 0);
    if (base + 3 < n) {
        v = *(const int4*)(deg + base);
        v.x += 1; v.y += 1; v.z += 1; v.w += 1;
    } else {
        if (base + 0 < n) v.x = deg[base + 0] + 1;
        if (base + 1 < n) v.y = deg[base + 1] + 1;
        if (base + 2 < n) v.z = deg[base + 2] + 1;
        if (base + 3 < n) v.w = deg[base + 3] + 1;
    }
    int mysum = v.x + v.y + v.z + v.w;
    int incl = mysum;
    #pragma unroll
    for (int off = 1; off < 32; off <<= 1) {
        int x = __shfl_up_sync(0xffffffffu, incl, off);
        if (lane >= off) incl += x;
    }
    if (lane == 31) wsum[wid] = incl;
    __syncthreads();
    if (wid == 0) {
        int w = wsum[lane];
        #pragma unroll
        for (int off = 1; off < 32; off <<= 1) {
            int x = __shfl_up_sync(0xffffffffu, w, off);
            if (lane >= off) w += x;
        }
        wsum[lane] = w;
    }
    __syncthreads();
    int excl = (wid ? wsum[wid - 1] : 0) + incl - mysum;
    int4 o;
    o.x = excl;
    o.y = o.x + v.x;
    o.z = o.y + v.y;
    o.w = o.z + v.z;
    if (base + 3 < n) {
        *(int4*)(rowptr + base) = o;
    } else {
        if (base + 0 < n) rowptr[base + 0] = o.x;
        if (base + 1 < n) rowptr[base + 1] = o.y;
        if (base + 2 < n) rowptr[base + 2] = o.z;
        if (base + 3 < n) rowptr[base + 3] = o.w;
    }
    if (t == 1023) blocksum[blockIdx.x] = wsum[31];
}

// ---------------- phase 2+3 fused ----------------
__global__ void scan3_kernel(int* __restrict__ rowptr, int* __restrict__ cursor,
                             const int* __restrict__ blocksum, int n, int nb) {
    __shared__ int soff[33];
    int t = threadIdx.x;
    if (t < 32) {
        int v = (t < nb) ? blocksum[t] : 0;
        int incl = v;
        #pragma unroll
        for (int off = 1; off < 32; off <<= 1) {
            int x = __shfl_up_sync(0xffffffffu, incl, off);
            if (t >= off) incl += x;
        }
        soff[t] = incl - v;
        if (t == 31) soff[32] = incl;
    }
    __syncthreads();
    int i = blockIdx.x * blockDim.x + t;
    if (i < n) {
        int val = rowptr[i] + soff[i / SCAN_TILE];
        rowptr[i] = val;
        cursor[i] = val;
    }
    if (blockIdx.x == 0 && t == 0) rowptr[n] = soff[32];
}

// ---------------- scatter ----------------
__global__ void scatter_kernel(const int* __restrict__ src, const int* __restrict__ dst,
                               const float4* __restrict__ aE0, const float4* __restrict__ aE1,
                               int* cursor, int* colsrc,
                               float4* __restrict__ aE0c, float4* __restrict__ aE1c,
                               int e, int n) {
    int i = blockIdx.x * blockDim.x + threadIdx.x;
    int tot = e + n;
    if (i >= tot) return;
    if (i < e) {
        int d = dst[i];
        int p = atomicAdd(&cursor[d], 1);
        colsrc[p] = src[i];
        aE0c[p] = aE0[i];
        aE1c[p] = aE1[i];
    } else {
        int node = i - e;
        int p = atomicAdd(&cursor[node], 1);
        colsrc[p] = node;
        aE0c[p] = g_self0;
        aE1c[p] = g_self1;
    }
}

// ---------------- fp16 tensor-core GEMM (cp.async 2-stage) + fused score epilogue -----
template <int SCOREC>
__global__ void hgemm_kernel(const __half* __restrict__ A, const __half* __restrict__ B,
                             __half* __restrict__ C, int M, int K, int N,
                             const float* __restrict__ asrc, const float* __restrict__ adst,
                             float* __restrict__ ssrc, float* __restrict__ sdst) {
    __shared__ __half As[2][128][40];
    __shared__ __half Bs[2][32][72];
    __shared__ float2 sred[128];
    const int AS_B = 128 * 40 * 2;
    const int BS_B = 32 * 72 * 2;
    int bm = blockIdx.y * 128, bn = blockIdx.x * 64;
    int tid = threadIdx.x;
    int wid = tid >> 5, lane = tid & 31;
    int wm = (wid >> 1) * 32, wn = (wid & 1) * 32;
    float acc[2][4][4];
    #pragma unroll
    for (int mt = 0; mt < 2; mt++)
        #pragma unroll
        for (int nt = 0; nt < 4; nt++)
            #pragma unroll
            for (int r = 0; r < 4; r++) acc[mt][nt][r] = 0.f;

    u32 as_base = (u32)__cvta_generic_to_shared(&As[0][0][0]);
    u32 bs_base = (u32)__cvta_generic_to_shared(&Bs[0][0][0]);

    int a_row0 = tid >> 2, a_c8 = (tid & 3) * 8;
    int b_row = tid >> 3, b_c8 = (tid & 7) * 8;

    {
        #pragma unroll
        for (int it = 0; it < 2; it++) {
            int row = a_row0 + it * 64;
            int gm = bm + row;
            int ok = (gm < M);
            const void* g = A + (size_t)(ok ? gm : 0) * K + a_c8;
            cp_async16(as_base + (u32)(row * 40 + a_c8) * 2, g, ok ? 16 : 0);
        }
        cp_async16(bs_base + (u32)(b_row * 72 + b_c8) * 2,
                   B + (size_t)b_row * N + bn + b_c8, 16);
        CP_COMMIT();
    }

    int KT = K >> 5;
    for (int kt = 0; kt < KT; kt++) {
        if (kt + 1 < KT) {
            int st = (kt + 1) & 1;
            int k0 = (kt + 1) * 32;
            #pragma unroll
            for (int it = 0; it < 2; it++) {
                int row = a_row0 + it * 64;
                int gm = bm + row;
                int ok = (gm < M);
                const void* g = A + (size_t)(ok ? gm : 0) * K + k0 + a_c8;
                cp_async16(as_base + (u32)(st * AS_B) + (u32)(row * 40 + a_c8) * 2, g, ok ? 16 : 0);
            }
            cp_async16(bs_base + (u32)(st * BS_B) + (u32)(b_row * 72 + b_c8) * 2,
                       B + (size_t)(k0 + b_row) * N + bn + b_c8, 16);
            CP_COMMIT();
            CP_WAIT(1);
        } else {
            CP_WAIT(0);
        }
        __syncthreads();
        u32 ab = as_base + (u32)((kt & 1) * AS_B);
        u32 bb = bs_base + (u32)((kt & 1) * BS_B);
        #pragma unroll
        for (int kk = 0; kk < 32; kk += 16) {
            u32 a0[4], a1[4], b0[4], b1[4];
            {
                int arow = wm + (lane & 15);
                int acol = kk + (lane >> 4) * 8;
                ldsm_x4(a0[0], a0[1], a0[2], a0[3], ab + (u32)(arow * 40 + acol) * 2);
            }
            {
                int arow = wm + 16 + (lane & 15);
                int acol = kk + (lane >> 4) * 8;
                ldsm_x4(a1[0], a1[1], a1[2], a1[3], ab + (u32)(arow * 40 + acol) * 2);
            }
            {
                int brow = kk + (lane & 15);
                int bcol = wn + (lane >> 4) * 8;
                ldsm_x4_trans(b0[0], b0[1], b0[2], b0[3], bb + (u32)(brow * 72 + bcol) * 2);
            }
            {
                int brow = kk + (lane & 15);
                int bcol = wn + 16 + (lane >> 4) * 8;
                ldsm_x4_trans(b1[0], b1[1], b1[2], b1[3], bb + (u32)(brow * 72 + bcol) * 2);
            }
            #pragma unroll
            for (int mt = 0; mt < 2; mt++) {
                u32* am = (mt == 0) ? a0 : a1;
                mma16816(acc[mt][0][0], acc[mt][0][1], acc[mt][0][2], acc[mt][0][3],
                         am[0], am[1], am[2], am[3], b0[0], b0[1]);
                mma16816(acc[mt][1][0], acc[mt][1][1], acc[mt][1][2], acc[mt][1][3],
                         am[0], am[1], am[2], am[3], b0[2], b0[3]);
                mma16816(acc[mt][2][0], acc[mt][2][1], acc[mt][2][2], acc[mt][2][3],
                         am[0], am[1], am[2], am[3], b1[0], b1[1]);
                mma16816(acc[mt][3][0], acc[mt][3][1], acc[mt][3][2], acc[mt][3][3],
                         am[0], am[1], am[2], am[3], b1[2], b1[3]);
            }
        }
        __syncthreads();
    }
    // store C
    #pragma unroll
    for (int mt = 0; mt < 2; mt++) {
        #pragma unroll
        for (int r = 0; r < 2; r++) {
            int row = bm + wm + mt * 16 + r * 8 + (lane >> 2);
            if (row < M) {
                #pragma unroll
                for (int nt = 0; nt < 4; nt++) {
                    __half2 h = __floats2half2_rn(acc[mt][nt][r * 2 + 0], acc[mt][nt][r * 2 + 1]);
                    *(__half2*)(C + (size_t)row * N + bn + wn + nt * 8 + (lane & 3) * 2) = h;
                }
            }
        }
    }
    if (SCOREC == 64) {
        int head = blockIdx.x;
        float asv[8], adv[8];
        #pragma unroll
        for (int nt = 0; nt < 4; nt++)
            #pragma unroll
            for (int c = 0; c < 2; c++) {
                int col = bn + wn + nt * 8 + (lane & 3) * 2 + c;
                asv[nt * 2 + c] = __ldg(asrc + col);
                adv[nt * 2 + c] = __ldg(adst + col);
            }
        float spv[4], dpv[4];
        #pragma unroll
        for (int mt = 0; mt < 2; mt++)
            #pragma unroll
            for (int r = 0; r < 2; r++) {
                float sp = 0.f, dp = 0.f;
                #pragma unroll
                for (int nt = 0; nt < 4; nt++)
                    #pragma unroll
                    for (int c = 0; c < 2; c++) {
                        float v = acc[mt][nt][r * 2 + c];
                        sp = fmaf(v, asv[nt * 2 + c], sp);
                        dp = fmaf(v, adv[nt * 2 + c], dp);
                    }
                sp += __shfl_down_sync(0xffffffffu, sp, 2, 4);
                sp += __shfl_down_sync(0xffffffffu, sp, 1, 4);
                dp += __shfl_down_sync(0xffffffffu, dp, 2, 4);
                dp += __shfl_down_sync(0xffffffffu, dp, 1, 4);
                spv[mt * 2 + r] = sp;
                dpv[mt * 2 + r] = dp;
            }
        if ((lane & 3) == 0 && (wid & 1)) {
            #pragma unroll
            for (int mt = 0; mt < 2; mt++)
                #pragma unroll
                for (int r = 0; r < 2; r++) {
                    int rl = wm + mt * 16 + r * 8 + (lane >> 2);
                    sred[rl] = make_float2(spv[mt * 2 + r], dpv[mt * 2 + r]);
                }
        }
        __syncthreads();
        if ((lane & 3) == 0 && !(wid & 1)) {
            #pragma unroll
            for (int mt = 0; mt < 2; mt++)
                #pragma unroll
                for (int r = 0; r < 2; r++) {
                    int rl = wm + mt * 16 + r * 8 + (lane >> 2);
                    float2 o = sred[rl];
                    int row = bm + rl;
                    if (row < M) {
                        ssrc[row * 4 + head] = spv[mt * 2 + r] + o.x;
                        sdst[row * 4 + head] = dpv[mt * 2 + r] + o.y;
                    }
                }
        }
    }
    if (SCOREC == 16) {
        int headA = wn >> 4, headB = headA + 1;
        float asv[8], adv[8];
        #pragma unroll
        for (int nt = 0; nt < 4; nt++)
            #pragma unroll
            for (int c = 0; c < 2; c++) {
                int col = bn + wn + nt * 8 + (lane & 3) * 2 + c;
                asv[nt * 2 + c] = __ldg(asrc + col);
                adv[nt * 2 + c] = __ldg(adst + col);
            }
        #pragma unroll
        for (int mt = 0; mt < 2; mt++)
            #pragma unroll
            for (int r = 0; r < 2; r++) {
                float spA = 0.f, dpA = 0.f, spB = 0.f, dpB = 0.f;
                #pragma unroll
                for (int c = 0; c < 2; c++) {
                    spA = fmaf(acc[mt][0][r * 2 + c], asv[0 * 2 + c], spA);
                    spA = fmaf(acc[mt][1][r * 2 + c], asv[1 * 2 + c], spA);
                    dpA = fmaf(acc[mt][0][r * 2 + c], adv[0 * 2 + c], dpA);
                    dpA = fmaf(acc[mt][1][r * 2 + c], adv[1 * 2 + c], dpA);
                    spB = fmaf(acc[mt][2][r * 2 + c], asv[2 * 2 + c], spB);
                    spB = fmaf(acc[mt][3][r * 2 + c], asv[3 * 2 + c], spB);
                    dpB = fmaf(acc[mt][2][r * 2 + c], adv[2 * 2 + c], dpB);
                    dpB = fmaf(acc[mt][3][r * 2 + c], adv[3 * 2 + c], dpB);
                }
                spA += __shfl_down_sync(0xffffffffu, spA, 2, 4);
                spA += __shfl_down_sync(0xffffffffu, spA, 1, 4);
                dpA += __shfl_down_sync(0xffffffffu, dpA, 2, 4);
                dpA += __shfl_down_sync(0xffffffffu, dpA, 1, 4);
                spB += __shfl_down_sync(0xffffffffu, spB, 2, 4);
                spB += __shfl_down_sync(0xffffffffu, spB, 1, 4);
                dpB += __shfl_down_sync(0xffffffffu, dpB, 2, 4);
                dpB += __shfl_down_sync(0xffffffffu, dpB, 1, 4);
                if ((lane & 3) == 0) {
                    int row = bm + wm + mt * 16 + r * 8 + (lane >> 2);
                    if (row < M) {
                        ssrc[row * 4 + headA] = spA;
                        sdst[row * 4 + headA] = dpA;
                        ssrc[row * 4 + headB] = spB;
                        sdst[row * 4 + headB] = dpB;
                    }
                }
            }
    }
}

// ---------------- 2-pass softmax + aggregation, warp/node, 4-edge unroll ----------------
template <int C, typename OutT>
__global__ void agg_kernel(const int* __restrict__ rowptr, const int* __restrict__ colsrc,
                           const float4* __restrict__ aEc,
                           const float4* __restrict__ ssrc, const float4* __restrict__ sdst,
                           const __half* __restrict__ hh, const float* __restrict__ bias,
                           float4* __restrict__ aCSR, OutT* __restrict__ outp, int n_nodes) {
    int warp = (blockIdx.x * blockDim.x + threadIdx.x) >> 5;
    int lane = threadIdx.x & 31;
    if (warp >= n_nodes) return;
    int node = warp;
    int base = rowptr[node], end = rowptr[node + 1];
    float4 sd = __ldg(sdst + node);
    int myhead = lane >> 3;
    float t0 = 0.f, t1 = 0.f, t2 = 0.f, t3 = 0.f;
    for (int j = base + lane; j < end; j += 32) {
        int s = colsrc[j];
        float4 ss = __ldg(ssrc + s);
        float4 ae = __ldg(aEc + j);
        float a0 = ss.x + sd.x + ae.x; a0 = a0 >= 0.f ? a0 : 0.2f * a0;
        float a1 = ss.y + sd.y + ae.y; a1 = a1 >= 0.f ? a1 : 0.2f * a1;
        float a2 = ss.z + sd.z + ae.z; a2 = a2 >= 0.f ? a2 : 0.2f * a2;
        float a3 = ss.w + sd.w + ae.w; a3 = a3 >= 0.f ? a3 : 0.2f * a3;
        float e0 = __expf(a0), e1 = __expf(a1);
        float e2 = __expf(a2), e3 = __expf(a3);
        aCSR[j] = make_float4(e0, e1, e2, e3);
        t0 += e0; t1 += e1; t2 += e2; t3 += e3;
    }
    #pragma unroll
    for (int off = 16; off; off >>= 1) {
        t0 += __shfl_xor_sync(0xffffffffu, t0, off);
        t1 += __shfl_xor_sync(0xffffffffu, t1, off);
        t2 += __shfl_xor_sync(0xffffffffu, t2, off);
        t3 += __shfl_xor_sync(0xffffffffu, t3, off);
    }
    float iv = 1.f / ((myhead == 0 ? t0 : myhead == 1 ? t1 : myhead == 2 ? t2 : t3) + 1e-16f);
    __syncwarp();
    const float* aS = (const float*)aCSR;
    if (C == 64) {
        float accA[8];
        #pragma unroll
        for (int k = 0; k < 8; k++) accA[k] = 0.f;
        int j = base;
        for (; j + 4 <= end; j += 4) {
            int s0 = colsrc[j], s1 = colsrc[j + 1], s2 = colsrc[j + 2], s3 = colsrc[j + 3];
            float e0 = __ldg(aS + (j + 0) * 4 + myhead);
            float e1 = __ldg(aS + (j + 1) * 4 + myhead);
            float e2 = __ldg(aS + (j + 2) * 4 + myhead);
            float e3 = __ldg(aS + (j + 3) * 4 + myhead);
            uint4 r0 = __ldg((const uint4*)(hh + (size_t)s0 * 256) + lane);
            uint4 r1 = __ldg((const uint4*)(hh + (size_t)s1 * 256) + lane);
            uint4 r2 = __ldg((const uint4*)(hh + (size_t)s2 * 256) + lane);
            uint4 r3 = __ldg((const uint4*)(hh + (size_t)s3 * 256) + lane);
            #pragma unroll
            for (int q = 0; q < 4; q++) {
                uint4 r = q == 0 ? r0 : q == 1 ? r1 : q == 2 ? r2 : r3;
                float ew = q == 0 ? e0 : q == 1 ? e1 : q == 2 ? e2 : e3;
                float2 f0 = __half22float2(*(__half2*)&r.x), f1 = __half22float2(*(__half2*)&r.y);
                float2 f2 = __half22float2(*(__half2*)&r.z), f3 = __half22float2(*(__half2*)&r.w);
                accA[0] = fmaf(f0.x, ew, accA[0]); accA[1] = fmaf(f0.y, ew, accA[1]);
                accA[2] = fmaf(f1.x, ew, accA[2]); accA[3] = fmaf(f1.y, ew, accA[3]);
                accA[4] = fmaf(f2.x, ew, accA[4]); accA[5] = fmaf(f2.y, ew, accA[5]);
                accA[6] = fmaf(f3.x, ew, accA[6]); accA[7] = fmaf(f3.y, ew, accA[7]);
            }
        }
        for (; j < end; j++) {
            int s = colsrc[j];
            float ew = __ldg(aS + j * 4 + myhead);
            uint4 r = __ldg((const uint4*)(hh + (size_t)s * 256) + lane);
            float2 f0 = __half22float2(*(__half2*)&r.x), f1 = __half22float2(*(__half2*)&r.y);
            float2 f2 = __half22float2(*(__half2*)&r.z), f3 = __half22float2(*(__half2*)&r.w);
            accA[0] = fmaf(f0.x, ew, accA[0]); accA[1] = fmaf(f0.y, ew, accA[1]);
            accA[2] = fmaf(f1.x, ew, accA[2]); accA[3] = fmaf(f1.y, ew, accA[3]);
            accA[4] = fmaf(f2.x, ew, accA[4]); accA[5] = fmaf(f2.y, ew, accA[5]);
            accA[6] = fmaf(f3.x, ew, accA[6]); accA[7] = fmaf(f3.y, ew, accA[7]);
        }
        float4 bv0 = *(const float4*)(bias + lane * 8);
        float4 bv1 = *(const float4*)(bias + lane * 8 + 4);
        float o0 = accA[0] * iv + bv0.x, o1 = accA[1] * iv + bv0.y;
        float o2 = accA[2] * iv + bv0.z, o3 = accA[3] * iv + bv0.w;
        float o4 = accA[4] * iv + bv1.x, o5 = accA[5] * iv + bv1.y;
        float o6 = accA[6] * iv + bv1.z, o7 = accA[7] * iv + bv1.w;
        if (sizeof(OutT) == 2) {
            __half2 h0 = __floats2half2_rn(o0, o1), h1 = __floats2half2_rn(o2, o3);
            __half2 h2 = __floats2half2_rn(o4, o5), h3 = __floats2half2_rn(o6, o7);
            uint4 pack;
            pack.x = *(u32*)&h0; pack.y = *(u32*)&h1; pack.z = *(u32*)&h2; pack.w = *(u32*)&h3;
            *(uint4*)((__half*)outp + (size_t)node * 256 + lane * 8) = pack;
        } else {
            float* op = (float*)outp + (size_t)node * 256 + lane * 8;
            *(float4*)op = make_float4(o0, o1, o2, o3);
            *(float4*)(op + 4) = make_float4(o4, o5, o6, o7);
        }
    } else {  // C == 16
        float2 acc = make_float2(0.f, 0.f);
        int j = base;
        for (; j + 4 <= end; j += 4) {
            int s0 = colsrc[j], s1 = colsrc[j + 1], s2 = colsrc[j + 2], s3 = colsrc[j + 3];
            float e0 = __ldg(aS + (j + 0) * 4 + myhead);
            float e1 = __ldg(aS + (j + 1) * 4 + myhead);
            float e2 = __ldg(aS + (j + 2) * 4 + myhead);
            float e3 = __ldg(aS + (j + 3) * 4 + myhead);
            float2 f0 = __half22float2(__ldg((const __half2*)(hh + (size_t)s0 * 64) + lane));
            float2 f1 = __half22float2(__ldg((const __half2*)(hh + (size_t)s1 * 64) + lane));
            float2 f2 = __half22float2(__ldg((const __half2*)(hh + (size_t)s2 * 64) + lane));
            float2 f3 = __half22float2(__ldg((const __half2*)(hh + (size_t)s3 * 64) + lane));
            acc.x = fmaf(f0.x, e0, acc.x); acc.y = fmaf(f0.y, e0, acc.y);
            acc.x = fmaf(f1.x, e1, acc.x); acc.y = fmaf(f1.y, e1, acc.y);
            acc.x = fmaf(f2.x, e2, acc.x); acc.y = fmaf(f2.y, e2, acc.y);
            acc.x = fmaf(f3.x, e3, acc.x); acc.y = fmaf(f3.y, e3, acc.y);
        }
        for (; j < end; j++) {
            int s = colsrc[j];
            float ew = __ldg(aS + j * 4 + myhead);
            float2 f = __half22float2(__ldg((const __half2*)(hh + (size_t)s * 64) + lane));
            acc.x = fmaf(f.x, ew, acc.x);
            acc.y = fmaf(f.y, ew, acc.y);
        }
        float2 bv = *(const float2*)(bias + 2 * lane);
        float ox = acc.x * iv + bv.x;
        float oy = acc.y * iv + bv.y;
        if (sizeof(OutT) == 2) {
            *(__half2*)((__half*)outp + (size_t)node * 64 + 2 * lane) = __floats2half2_rn(ox, oy);
        } else {
            *(float2*)((float*)outp + (size_t)node * 64 + 2 * lane) = make_float2(ox, oy);
        }
    }
}

// ---------------- launch ----------------
extern "C" void kernel_launch(void* const* d_in, const int* in_sizes, int n_in,
                              void* d_out, int out_size) {
    const float* x   = (const float*)d_in[0];
    const int*   ei  = (const int*)d_in[1];
    const float* ts  = (const float*)d_in[2];
    const float* tw  = (const float*)d_in[3];
    const float* tb  = (const float*)d_in[4];
    const float* W0  = (const float*)d_in[5];
    const float* as0 = (const float*)d_in[6];
    const float* ad0 = (const float*)d_in[7];
    const float* le0 = (const float*)d_in[8];
    const float* ae0 = (const float*)d_in[9];
    const float* b0  = (const float*)d_in[10];
    const float* W1  = (const float*)d_in[11];
    const float* as1 = (const float*)d_in[12];
    const float* ad1 = (const float*)d_in[13];
    const float* le1 = (const float*)d_in[14];
    const float* ae1 = (const float*)d_in[15];
    const float* b1  = (const float*)d_in[16];

    int n = in_sizes[0] / 128;   // 50000
    int e = in_sizes[2];         // 800000
    int tot = e + n;
    const int* srcp = ei;
    const int* dstp = ei + e;

    void *p_xh, *p_w0h, *p_w1h, *p_hh0, *p_out0h, *p_hh1;
    void *p_aE0, *p_aE1, *p_aE0c, *p_aE1c, *p_aCSR, *p_ss0, *p_sd0, *p_ss1, *p_sd1;
    void *p_deg, *p_rowptr, *p_cursor, *p_colsrc, *p_bsum;
    cudaGetSymbolAddress(&p_xh, g_xh);
    cudaGetSymbolAddress(&p_w0h, g_w0h);
    cudaGetSymbolAddress(&p_w1h, g_w1h);
    cudaGetSymbolAddress(&p_hh0, g_hh0);
    cudaGetSymbolAddress(&p_out0h, g_out0h);
    cudaGetSymbolAddress(&p_hh1, g_hh1);
    cudaGetSymbolAddress(&p_aE0, g_alphaE0);
    cudaGetSymbolAddress(&p_aE1, g_alphaE1);
    cudaGetSymbolAddress(&p_aE0c, g_aE0c);
    cudaGetSymbolAddress(&p_aE1c, g_aE1c);
    cudaGetSymbolAddress(&p_aCSR, g_aCSR);
    cudaGetSymbolAddress(&p_ss0, g_ss0);
    cudaGetSymbolAddress(&p_sd0, g_sd0);
    cudaGetSymbolAddress(&p_ss1, g_ss1);
    cudaGetSymbolAddress(&p_sd1, g_sd1);
    cudaGetSymbolAddress(&p_deg, g_deg);
    cudaGetSymbolAddress(&p_rowptr, g_rowptr);
    cudaGetSymbolAddress(&p_cursor, g_cursor);
    cudaGetSymbolAddress(&p_colsrc, g_colsrc);
    cudaGetSymbolAddress(&p_bsum, g_blocksum);

    __half* xh     = (__half*)p_xh;
    __half* w0h    = (__half*)p_w0h;
    __half* w1h    = (__half*)p_w1h;
    __half* hh0    = (__half*)p_hh0;
    __half* out0h  = (__half*)p_out0h;
    __half* hh1    = (__half*)p_hh1;
    float4* aE0    = (float4*)p_aE0;
    float4* aE1    = (float4*)p_aE1;
    float4* aE0c   = (float4*)p_aE0c;
    float4* aE1c   = (float4*)p_aE1c;
    float4* aCSR   = (float4*)p_aCSR;
    float4* ss0    = (float4*)p_ss0;
    float4* sd0    = (float4*)p_sd0;
    float4* ss1    = (float4*)p_ss1;
    float4* sd1    = (float4*)p_sd1;
    int* deg       = (int*)p_deg;
    int* rowptr    = (int*)p_rowptr;
    int* cursor    = (int*)p_cursor;
    int* colsrc    = (int*)p_colsrc;
    int* bsum      = (int*)p_bsum;

    int nb = (n + SCAN_TILE - 1) / SCAN_TILE;   // 13 for n=50000

    static cudaStream_t s1 = 0;
    static cudaEvent_t evFork = 0, evJoin = 0;
    if (s1 == 0) {
        cudaStreamCreateWithFlags(&s1, cudaStreamNonBlocking);
        cudaEventCreateWithFlags(&evFork, cudaEventDisableTiming);
        cudaEventCreateWithFlags(&evJoin, cudaEventDisableTiming);
    }

    // fork immediately: s1 runs cvt -> hgemm0 (independent of CSR chain)
    cudaEventRecord(evFork, 0);
    cudaStreamWaitEvent(s1, evFork, 0);
    cvt_kernel<<<512, 256, 0, s1>>>(x, W0, W1, xh, w0h, w1h, n);
    hgemm_kernel<64><<<dim3(256 / 64, (n + 127) / 128), 256, 0, s1>>>(
        xh, w0h, hh0, n, 128, 256, as0, ad0, (float*)ss0, (float*)sd0);
    cudaEventRecord(evJoin, s1);

    // main: CSR chain starts right away
    cudaMemsetAsync(deg, 0, (size_t)n * sizeof(int), 0);
    prep_kernel<<<1, 256>>>(le0, ae0, le1, ae1);
    edge_feat_kernel<<<(e + 1023) / 1024, 256>>>(ts, tw, tb, dstp, deg, aE0, aE1, e);
    scan1_kernel<<<nb, 1024>>>(deg, rowptr, bsum, n);
    scan3_kernel<<<(n + 255) / 256, 256>>>(rowptr, cursor, bsum, n, nb);
    scatter_kernel<<<(tot + 255) / 256, 256>>>(srcp, dstp, aE0, aE1, cursor, colsrc,
                                               aE0c, aE1c, e, n);
    // join: agg0 needs hh0/ss0/sd0 from s1 + CSR from main
    cudaStreamWaitEvent(0, evJoin, 0);
    agg_kernel<64, __half><<<(n * 32 + 255) / 256, 256>>>(rowptr, colsrc, aE0c, ss0, sd0,
                                                          hh0, b0, aCSR, out0h, n);
    hgemm_kernel<16><<<dim3(64 / 64, (n + 127) / 128), 256>>>(
        out0h, w1h, hh1, n, 256, 64, as1, ad1, (float*)ss1, (float*)sd1);
    agg_kernel<16, float><<<(n * 32 + 255) / 256, 256>>>(rowptr, colsrc, aE1c, ss1, sd1,
                                                         hh1, b1, aCSR, (float*)d_out, n);
}